// round 2
// baseline (speedup 1.0000x reference)
#include <cuda_runtime.h>

#define TT 4096
#define BB 64
#define HH 512
#define GRID 128
#define NTHREADS 128
#define KTOT 576        // 512 (h) + 64 (x)
#define WSTRIDE 584     // padded row stride to avoid bank aliasing
#define HB (HH*BB)      // 32768 floats per h buffer

// Global scratch (allocation-free rules: __device__ globals)
__device__ __align__(16) float g_hbuf[2*HB];
__device__ int g_flags[GRID];

__device__ __forceinline__ float sigf(float x){ return 1.f/(1.f+__expf(-x)); }
__device__ __forceinline__ float tanhf_fast(float x){
    // overflow-safe tanh via exp of negative argument
    float e = __expf(-2.f*fabsf(x));
    float r = (1.f-e)/(1.f+e);
    return copysignf(r, x);
}

__device__ __forceinline__ void cp16(unsigned dst, const void* src){
    asm volatile("cp.async.cg.shared.global [%0], [%1], 16;\n"::"r"(dst),"l"(src));
}
__device__ __forceinline__ void cp_commit(){ asm volatile("cp.async.commit_group;\n"::); }
#define CP_WAIT(N) asm volatile("cp.async.wait_group %0;\n"::"n"(N))

__global__ void __launch_bounds__(128,1) stn_init_kernel(){
    int i = blockIdx.x*blockDim.x + threadIdx.x;
    if (i < 2*HB) g_hbuf[i] = 0.f;
    if (i < GRID) g_flags[i] = 0;
}

__device__ __forceinline__ void gemm_range(const float* __restrict__ sH,
                                           const float* __restrict__ wrow0,
                                           int k0, int k1, int bq,
                                           float4& a0, float4& a1){
#pragma unroll 8
    for (int k = k0; k < k1; ++k){
        float4 hv = *reinterpret_cast<const float4*>(sH + k*BB + (bq<<2));
        float w0 = wrow0[k];
        float w1 = wrow0[WSTRIDE + k];
        a0.x = fmaf(w0, hv.x, a0.x);
        a0.y = fmaf(w0, hv.y, a0.y);
        a0.z = fmaf(w0, hv.z, a0.z);
        a0.w = fmaf(w0, hv.w, a0.w);
        a1.x = fmaf(w1, hv.x, a1.x);
        a1.y = fmaf(w1, hv.y, a1.y);
        a1.z = fmaf(w1, hv.z, a1.z);
        a1.w = fmaf(w1, hv.w, a1.w);
    }
}

__global__ void __launch_bounds__(NTHREADS,1) stn_kernel(
    const float* __restrict__ x,      // [64,4096,64]
    const float* __restrict__ W_ih,   // [2048,64]
    const float* __restrict__ W_hh,   // [2048,512]
    const float* __restrict__ b_ih,   // [2048]
    const float* __restrict__ b_hh,   // [2048]
    float* __restrict__ out_states,   // [64,4096,512]
    float* __restrict__ out_final)    // [64,1024]
{
    extern __shared__ float smem[];
    float* sH = smem;                    // [576][64]  36864 floats
    float* sW = sH + KTOT*BB;            // [16][584]   9344 floats
    float* sG = sW + 16*WSTRIDE;         // [16][64]    1024 floats
    float* sB = sG + 16*BB;              // [16]
    float* sC = sB + 16;                 // [4][64]      256 floats

    const int tid = threadIdx.x;
    const int u0  = blockIdx.x * 4;      // this CTA's 4 hidden units

    // ---- load weights once: local row lr = gate*4 + j  -> global row gate*512 + u0 + j
    for (int idx = tid; idx < 16*KTOT; idx += NTHREADS){
        int lr = idx / KTOT, k = idx - lr*KTOT;
        int g = lr >> 2, j = lr & 3;
        int gr = g*HH + u0 + j;
        float w = (k < HH) ? W_hh[(size_t)gr*HH + k] : W_ih[gr*64 + (k - HH)];
        sW[lr*WSTRIDE + k] = w;
    }
    if (tid < 16){
        int g = tid >> 2, j = tid & 3;
        int gr = g*HH + u0 + j;
        sB[tid] = b_ih[gr] + b_hh[gr];
    }
    for (int idx = tid; idx < 4*BB; idx += NTHREADS) sC[idx] = 0.f;
    __syncthreads();

    const unsigned sH_addr = (unsigned)__cvta_generic_to_shared(sH);
    const int bq = tid & 15;             // batch-quad 0..15
    const int r0 = (tid >> 4) << 1;      // rows {r0, r0+1}
    const float* wrow0 = sW + r0*WSTRIDE;
    const int bx = tid >> 1, half = tid & 1;   // x staging assignment

    for (int t = 0; t < TT; ++t){
        const float* hsrc = g_hbuf + (size_t)(t & 1)*HB;

        // issue async copy of full h (4 chunks of 128 unit-rows), overlapped with compute
#pragma unroll
        for (int c = 0; c < 4; ++c){
#pragma unroll
            for (int i = 0; i < 16; ++i){
                int v = c*2048 + i*128 + tid;   // float4 index
                cp16(sH_addr + v*16, hsrc + v*4);
            }
            cp_commit();
        }

        // x_t loads into registers (needed only for k>=512, DRAM latency hidden)
        const float* xp = x + ((size_t)bx*TT + t)*64 + half*32;
        float4 xr[8];
#pragma unroll
        for (int i = 0; i < 8; ++i) xr[i] = *reinterpret_cast<const float4*>(xp + i*4);

        float4 a0 = make_float4(0.f,0.f,0.f,0.f);
        float4 a1 = make_float4(0.f,0.f,0.f,0.f);

        CP_WAIT(3); __syncthreads();
        gemm_range(sH, wrow0,   0, 128, bq, a0, a1);
        CP_WAIT(2); __syncthreads();
        gemm_range(sH, wrow0, 128, 256, bq, a0, a1);
        CP_WAIT(1); __syncthreads();
        gemm_range(sH, wrow0, 256, 384, bq, a0, a1);
        CP_WAIT(0); __syncthreads();
        gemm_range(sH, wrow0, 384, 512, bq, a0, a1);

        // stage x_t (transposed) into sH rows 512..575
#pragma unroll
        for (int i = 0; i < 8; ++i){
            int ib = half*32 + i*4;
            sH[(HH+ib  )*BB + bx] = xr[i].x;
            sH[(HH+ib+1)*BB + bx] = xr[i].y;
            sH[(HH+ib+2)*BB + bx] = xr[i].z;
            sH[(HH+ib+3)*BB + bx] = xr[i].w;
        }
        __syncthreads();
        gemm_range(sH, wrow0, 512, 576, bq, a0, a1);

        *reinterpret_cast<float4*>(sG + r0*BB     + (bq<<2)) = a0;
        *reinterpret_cast<float4*>(sG + (r0+1)*BB + (bq<<2)) = a1;
        __syncthreads();

        // ---- epilogue: 64 threads, one batch each, 4 units
        if (tid < BB){
            int b = tid;
            float h2a[4], c2a[4];
#pragma unroll
            for (int j = 0; j < 4; ++j){
                float gi = sG[(     j)*BB + b] + sB[j];
                float gf = sG[( 4 + j)*BB + b] + sB[4+j];
                float gg = sG[( 8 + j)*BB + b] + sB[8+j];
                float go = sG[(12 + j)*BB + b] + sB[12+j];
                float iv = sigf(gi), fv = sigf(gf);
                float gv = tanhf_fast(gg), ov = sigf(go);
                float cold = sC[j*BB + b];
                float hold = sH[(u0+j)*BB + b];
                float cn = fv*cold + iv*gv;
                float hn = ov*tanhf_fast(cn);
                float h2 = 0.5f*(hold + hn);   // K = 0.5 Euler blend
                float c2 = 0.5f*(cold + cn);
                sC[j*BB + b] = c2;
                g_hbuf[(size_t)((t+1)&1)*HB + (u0+j)*BB + b] = h2;
                h2a[j] = h2; c2a[j] = c2;
            }
            float4 hv4 = make_float4(h2a[0],h2a[1],h2a[2],h2a[3]);
            *reinterpret_cast<float4*>(out_states + ((size_t)b*TT + t)*HH + u0) = hv4;
            if (t == TT-1){
                float4 cv4 = make_float4(c2a[0],c2a[1],c2a[2],c2a[3]);
                *reinterpret_cast<float4*>(out_final + b*(2*HH) + u0) = hv4;
                *reinterpret_cast<float4*>(out_final + b*(2*HH) + HH + u0) = cv4;
            }
        }

        // ---- grid-wide step barrier (release/acquire flags, all CTAs co-resident)
        if (t != TT-1){
            __syncthreads();
            if (tid == 0){
                asm volatile("st.release.gpu.global.u32 [%0], %1;\n"
                             :: "l"(&g_flags[blockIdx.x]), "r"((unsigned)(t+1)) : "memory");
            }
            unsigned v;
            const int* fp = &g_flags[tid];   // NTHREADS == GRID
            do {
                asm volatile("ld.acquire.gpu.global.u32 %0, [%1];\n"
                             : "=r"(v) : "l"(fp) : "memory");
            } while (v < (unsigned)(t+1));
            __syncthreads();
        }
    }
}

extern "C" void kernel_launch(void* const* d_in, const int* in_sizes, int n_in,
                              void* d_out, int out_size)
{
    const float* x    = (const float*)d_in[0];
    const float* W_ih = (const float*)d_in[1];
    const float* W_hh = (const float*)d_in[2];
    const float* b_ih = (const float*)d_in[3];
    const float* b_hh = (const float*)d_in[4];
    float* out        = (float*)d_out;
    float* out_final  = out + (size_t)BB*TT*HH;

    const int smem_bytes = (KTOT*BB + 16*WSTRIDE + 16*BB + 16 + 4*BB) * 4;  // 190016
    cudaFuncSetAttribute(stn_kernel, cudaFuncAttributeMaxDynamicSharedMemorySize, smem_bytes);

    stn_init_kernel<<<(2*HB + 127)/128, 128>>>();
    stn_kernel<<<GRID, NTHREADS, smem_bytes>>>(x, W_ih, W_hh, b_ih, b_hh, out, out_final);
}